// round 4
// baseline (speedup 1.0000x reference)
#include <cuda_runtime.h>
#include <cstdint>

// Problem constants
#define M 64
#define K 4096
#define N 11008
#define GROUP 128
#define NGROUPS 32

// Tiling
#define NTILE 128              // output columns per block
#define KSPLIT 8               // K-dimension split across blockIdx.y
#define KB (K / KSPLIT)        // 512 k per block
#define GPB (KB / GROUP)       // 4 quant groups per block
#define THREADS 256            // 8 row-groups (warps) x 32 column-threads

// ---------------------------------------------------------------------------
// Init: out[m][n] = bias[n]  (out is poisoned; main kernel atomically adds)
// ---------------------------------------------------------------------------
__global__ void init_out_kernel(const float* __restrict__ bias,
                                float* __restrict__ out) {
    int idx = blockIdx.x * blockDim.x + threadIdx.x;
    if (idx < M * N) out[idx] = bias[idx % N];
}

// ---------------------------------------------------------------------------
// Main GPTQ int4 dequant-GEMM.
//   out[m][n] += sum_{k in this block's K slice} x[m][k] * W[k][n]
//   W[k][n] = scales[g][n] * (q[k][n] - z[g][n]),  g = k/128
// Per-thread tile: 8 rows x 4 cols. Weight dequant uses the 2^23 magic
// constant (LOP3+FADD, no I2F) with per-group (s, s*z) folded into one FFMA.
// ---------------------------------------------------------------------------
__global__ __launch_bounds__(THREADS, 2)
void gptq_gemm_kernel(const float* __restrict__ x,
                      const int*   __restrict__ qweight,   // [K/8, N]
                      const int*   __restrict__ qzeros,    // [NGROUPS, N/8]
                      const float* __restrict__ scales,    // [NGROUPS, N]
                      float*       __restrict__ out) {
    __shared__ float xs[M][GROUP];                // 64 x 128 f32 = 32 KB

    const int tid = threadIdx.x;
    const int rg  = tid >> 5;                     // row group = warp id (0..7)
    const int ct  = tid & 31;                     // column thread (0..31)
    const int m0  = rg * 8;                       // first of my 8 rows
    const int nb  = blockIdx.x * NTILE + ct * 4;  // first of my 4 columns
    const int kblock = blockIdx.y;
    const int k0  = kblock * KB;

    float acc[8][4];
#pragma unroll
    for (int i = 0; i < 8; i++)
#pragma unroll
        for (int c = 0; c < 4; c++) acc[i][c] = 0.0f;

    for (int gl = 0; gl < GPB; gl++) {
        const int g   = kblock * GPB + gl;        // global quant group
        const int gk0 = k0 + gl * GROUP;          // first k of this group

        __syncthreads();                          // protect xs from prev group
        // Cooperative load of x[0:64][gk0:gk0+128] into SMEM.
        // Consecutive tid -> consecutive k: coalesced LDG, conflict-free STS.
#pragma unroll
        for (int t = 0; t < (M * GROUP) / THREADS; t++) {   // 32 iterations
            int idx = t * THREADS + tid;
            int m   = idx >> 7;                   // / GROUP
            int k   = idx & (GROUP - 1);
            xs[m][k] = x[m * K + gk0 + k];
        }
        __syncthreads();

        // Per-group scale and folded scale*zero for my 4 columns.
        const float4 s4 = *reinterpret_cast<const float4*>(&scales[(size_t)g * N + nb]);
        float s[4]  = {s4.x, s4.y, s4.z, s4.w};
        const unsigned zw = (unsigned)qzeros[g * (N / 8) + (nb >> 3)];
        float sz[4];
#pragma unroll
        for (int c = 0; c < 4; c++) {
            float zf = (float)(((zw >> (4 * ((nb + c) & 7))) & 15u) + 1u);
            sz[c] = s[c] * zf;
        }

        const int* qrow = qweight + (size_t)(gk0 >> 3) * N + nb;

#pragma unroll 1
        for (int k8 = 0; k8 < GROUP / 8; k8++) {  // 16 packed rows per group
            const int4 qw = *reinterpret_cast<const int4*>(qrow + (size_t)k8 * N);
            const unsigned q[4] = {(unsigned)qw.x, (unsigned)qw.y,
                                   (unsigned)qw.z, (unsigned)qw.w};
#pragma unroll
            for (int j = 0; j < 8; j++) {         // nibble within packed word
                float w[4];
#pragma unroll
                for (int c = 0; c < 4; c++) {
                    // q as exact fp32 via magic constant: (2^23 | q) - 2^23
                    float qf = __uint_as_float(0x4B000000u | ((q[c] >> (4 * j)) & 15u))
                               - 8388608.0f;
                    w[c] = fmaf(s[c], qf, -sz[c]);   // scale*(q - z)
                }
                const int kk = k8 * 8 + j;
#pragma unroll
                for (int i = 0; i < 8; i++) {
                    const float xv = xs[m0 + i][kk];  // warp-uniform broadcast LDS
#pragma unroll
                    for (int c = 0; c < 4; c++)
                        acc[i][c] = fmaf(xv, w[c], acc[i][c]);
                }
            }
        }
    }

    // Epilogue: accumulate this K-slice's partials into out (bias pre-written).
#pragma unroll
    for (int i = 0; i < 8; i++) {
        float* orow = out + (size_t)(m0 + i) * N + nb;
#pragma unroll
        for (int c = 0; c < 4; c++)
            atomicAdd(orow + c, acc[i][c]);
    }
}

// ---------------------------------------------------------------------------
// kernel_launch: inputs per metadata order: x, qweight, qzeros, scales, bias
// ---------------------------------------------------------------------------
extern "C" void kernel_launch(void* const* d_in, const int* in_sizes, int n_in,
                              void* d_out, int out_size) {
    (void)in_sizes; (void)n_in; (void)out_size;
    const float* x       = (const float*)d_in[0];
    const int*   qweight = (const int*)  d_in[1];
    const int*   qzeros  = (const int*)  d_in[2];
    const float* scales  = (const float*)d_in[3];
    const float* bias    = (const float*)d_in[4];
    float*       out     = (float*)d_out;

    init_out_kernel<<<(M * N + 255) / 256, 256>>>(bias, out);

    dim3 grid(N / NTILE, KSPLIT);                 // (86, 8) = 688 blocks
    gptq_gemm_kernel<<<grid, THREADS>>>(x, qweight, qzeros, scales, out);
}

// round 9
// speedup vs baseline: 3.4419x; 3.4419x over previous
#include <cuda_runtime.h>
#include <cuda_fp16.h>
#include <cstdint>

#define M 64
#define K 4096
#define N 11008
#define GROUP 128
#define NGROUPS 32

#define NTILE 64            // n-cols per CTA  -> 172 n-tiles
#define KSPLIT 4            // k-split          -> grid (172, 4)
#define GPB (NGROUPS / KSPLIT)   // 8 groups per CTA
#define THREADS 128         // 4 warps, each owns n16 x m64

// SMEM rows padded to 272B (17 x 16B) -> ldmatrix conflict-free
#define LDA 272
#define AH_OFF 0
#define AL_OFF 17408
#define W_OFF  34816
#define SMEM_BYTES 52224

// Pre-split, k-permuted activations: rows 0..63 = fp16 hi(x), 64..127 = fp16 lo(x)
__device__ __half g_xsplit[128 * K];

// ---------------------------------------------------------------------------
__global__ void init_out_kernel(const float* __restrict__ bias,
                                float* __restrict__ out) {
    int idx = blockIdx.x * blockDim.x + threadIdx.x;
    if (idx < M * N) out[idx] = bias[idx % N];
}

// Split x into fp16 hi/lo, permute k within each 8-block: [0,4,1,5,2,6,3,7]
__global__ void prep_x_kernel(const float* __restrict__ x) {
    int i = blockIdx.x * blockDim.x + threadIdx.x;   // 64 * 512 = 32768 threads
    if (i >= M * (K / 8)) return;
    int m = i >> 9, b = i & 511;
    const float* src = x + m * K + b * 8;
    float f[8];
#pragma unroll
    for (int j = 0; j < 8; ++j) f[j] = src[j];

    const int perm[8] = {0, 4, 1, 5, 2, 6, 3, 7};    // permuted pos p holds f[perm[p]]
    __half h[8], l[8];
#pragma unroll
    for (int p = 0; p < 8; ++p) {
        float v = f[perm[p]];
        __half hi = __float2half(v);
        h[p] = hi;
        l[p] = __float2half(v - __half2float(hi));
    }
    *reinterpret_cast<uint4*>(g_xsplit + (size_t)m * K + b * 8) =
        *reinterpret_cast<uint4*>(h);
    *reinterpret_cast<uint4*>(g_xsplit + (size_t)(m + 64) * K + b * 8) =
        *reinterpret_cast<uint4*>(l);
}

// ---------------------------------------------------------------------------
__device__ __forceinline__ uint32_t smem_u32(const void* p) {
    uint32_t a;
    asm("{ .reg .u64 t; cvta.to.shared.u64 t, %1; cvt.u32.u64 %0, t; }" : "=r"(a) : "l"(p));
    return a;
}
#define LDSM_X4(r0, r1, r2, r3, a)                                              \
    asm volatile("ldmatrix.sync.aligned.m8n8.x4.shared.b16 {%0,%1,%2,%3}, [%4];" \
                 : "=r"(r0), "=r"(r1), "=r"(r2), "=r"(r3) : "r"(a))
#define MMA16816(c, a0, a1, a2, a3, b0, b1)                                     \
    asm volatile("mma.sync.aligned.m16n8k16.row.col.f32.f16.f16.f32 "           \
                 "{%0,%1,%2,%3}, {%4,%5,%6,%7}, {%8,%9}, {%0,%1,%2,%3};"        \
                 : "+f"((c)[0]), "+f"((c)[1]), "+f"((c)[2]), "+f"((c)[3])       \
                 : "r"(a0), "r"(a1), "r"(a2), "r"(a3), "r"(b0), "r"(b1))

__global__ __launch_bounds__(THREADS, 2)
void gptq_mma_kernel(const int*   __restrict__ qweight,   // [K/8, N]
                     const int*   __restrict__ qzeros,    // [NGROUPS, N/8]
                     const float* __restrict__ scales,    // [NGROUPS, N]
                     float*       __restrict__ out) {
    extern __shared__ char smem[];
    const uint32_t sb = smem_u32(smem);
    const int tid  = threadIdx.x;
    const int wid  = tid >> 5;
    const int lane = tid & 31;
    const int tig  = lane & 3;                  // thread-in-group (mma)
    const int nb0  = blockIdx.x * NTILE;
    const int g0   = blockIdx.y * GPB;          // first quant group for this CTA

    // dequant role: column + qrow half
    const int nloc  = tid & 63;                 // 0..63
    const int nG    = nb0 + nloc;
    const int qrhalf = tid >> 6;                // 0/1 -> qrows 0-7 / 8-15 of group

    // ldmatrix lane offsets
    const int rowA  = lane & 15;                                   // A x4 pattern
    const uint32_t aLane = (uint32_t)rowA * LDA + ((lane >> 4) << 4);
    const int nrowB = (lane & 7) | ((lane >> 1) & 8);              // B x4 pattern
    const uint32_t bLane = (uint32_t)(wid * 16 + nrowB) * LDA + ((lane & 8) ? 16u : 0u);

    float P[4][2][4];      // per-group partials (hi+lo share)
    float Ms[4][2][4];     // fp32 masters
#pragma unroll
    for (int mt = 0; mt < 4; ++mt)
#pragma unroll
        for (int j = 0; j < 2; ++j)
#pragma unroll
            for (int c = 0; c < 4; ++c) { P[mt][j][c] = 0.f; Ms[mt][j][c] = 0.f; }

    for (int gi = 0; gi < GPB; ++gi) {
        const int g   = g0 + gi;
        const int kg0 = g * GROUP;              // global k of group start

        __syncthreads();                        // smem reuse barrier

        // ---- stage A: 128 rows (hi 0-63, lo 64-127) x 128 k (fp16) ----------
#pragma unroll
        for (int p = 0; p < 16; ++p) {
            int idx = p * THREADS + tid;        // 2048 16B-chunks
            int row = idx >> 4, ch = idx & 15;
            uint4 v = *reinterpret_cast<const uint4*>(
                g_xsplit + (size_t)row * K + kg0 + ch * 8);
            uint32_t dst = (row < 64) ? (AH_OFF + row * LDA) : (AL_OFF + (row - 64) * LDA);
            *reinterpret_cast<uint4*>(smem + dst + ch * 16) = v;
        }

        // ---- dequant W -> smem [64 n][128 k] fp16, integer-exact ------------
        {
            const unsigned zw = (unsigned)qzeros[g * (N / 8) + (nG >> 3)];
            const unsigned znib = (zw >> (4 * (nG & 7))) & 15u;
            const unsigned zc  = 0x6400u + znib + 1u;      // fp16(1024 + zero)
            const unsigned zc2 = zc | (zc << 16);
            const int qrow0 = (kg0 >> 3) + qrhalf * 8;
#pragma unroll
            for (int j = 0; j < 8; ++j) {
                const unsigned q = (unsigned)qweight[(size_t)(qrow0 + j) * N + nG];
                unsigned r0 = (q          & 0x000F000Fu) | 0x64006400u;  // nib0,nib4
                unsigned r1 = ((q >> 4)   & 0x000F000Fu) | 0x64006400u;  // nib1,nib5
                unsigned r2 = ((q >> 8)   & 0x000F000Fu) | 0x64006400u;  // nib2,nib6
                unsigned r3 = ((q >> 12)  & 0x000F000Fu) | 0x64006400u;  // nib3,nib7
                unsigned w0, w1, w2, w3;
                asm("sub.rn.f16x2 %0, %1, %2;" : "=r"(w0) : "r"(r0), "r"(zc2));
                asm("sub.rn.f16x2 %0, %1, %2;" : "=r"(w1) : "r"(r1), "r"(zc2));
                asm("sub.rn.f16x2 %0, %1, %2;" : "=r"(w2) : "r"(r2), "r"(zc2));
                asm("sub.rn.f16x2 %0, %1, %2;" : "=r"(w3) : "r"(r3), "r"(zc2));
                uint32_t a = sb + W_OFF + (uint32_t)nloc * LDA + (qrhalf * 8 + j) * 16;
                asm volatile("st.shared.v4.b32 [%0], {%1,%2,%3,%4};"
                             :: "r"(a), "r"(w0), "r"(w1), "r"(w2), "r"(w3) : "memory");
            }
        }
        __syncthreads();

        // ---- compute: 8 k16 steps -------------------------------------------
#pragma unroll 1
        for (int st = 0; st < 8; ++st) {
            const uint32_t so = (uint32_t)st * 32;     // k16 -> 32 bytes
            uint32_t b0, b1, b2, b3;
            LDSM_X4(b0, b1, b2, b3, sb + W_OFF + bLane + so);
#pragma unroll
            for (int mt = 0; mt < 4; ++mt) {
                uint32_t a0, a1, a2, a3;
                LDSM_X4(a0, a1, a2, a3, sb + AH_OFF + (uint32_t)mt * (16 * LDA) + so + aLane);
                MMA16816(P[mt][0], a0, a1, a2, a3, b0, b1);
                MMA16816(P[mt][1], a0, a1, a2, a3, b2, b3);
                LDSM_X4(a0, a1, a2, a3, sb + AL_OFF + (uint32_t)mt * (16 * LDA) + so + aLane);
                MMA16816(P[mt][0], a0, a1, a2, a3, b0, b1);
                MMA16816(P[mt][1], a0, a1, a2, a3, b2, b3);
            }
        }

        // ---- per-group scale apply ------------------------------------------
        {
            const int n0 = nb0 + wid * 16 + 2 * tig;   // tile0 cols
            const float s00 = scales[(size_t)g * N + n0];
            const float s01 = scales[(size_t)g * N + n0 + 1];
            const float s10 = scales[(size_t)g * N + n0 + 8];
            const float s11 = scales[(size_t)g * N + n0 + 9];
#pragma unroll
            for (int mt = 0; mt < 4; ++mt) {
                Ms[mt][0][0] = fmaf(s00, P[mt][0][0], Ms[mt][0][0]);
                Ms[mt][0][1] = fmaf(s01, P[mt][0][1], Ms[mt][0][1]);
                Ms[mt][0][2] = fmaf(s00, P[mt][0][2], Ms[mt][0][2]);
                Ms[mt][0][3] = fmaf(s01, P[mt][0][3], Ms[mt][0][3]);
                Ms[mt][1][0] = fmaf(s10, P[mt][1][0], Ms[mt][1][0]);
                Ms[mt][1][1] = fmaf(s11, P[mt][1][1], Ms[mt][1][1]);
                Ms[mt][1][2] = fmaf(s10, P[mt][1][2], Ms[mt][1][2]);
                Ms[mt][1][3] = fmaf(s11, P[mt][1][3], Ms[mt][1][3]);
#pragma unroll
                for (int j = 0; j < 2; ++j)
#pragma unroll
                    for (int c = 0; c < 4; ++c) P[mt][j][c] = 0.f;
            }
        }
    }

    // ---- epilogue: accumulate into bias-initialized out ---------------------
    {
        const int n0 = nb0 + wid * 16 + 2 * tig;
        const int r  = lane >> 2;
#pragma unroll
        for (int mt = 0; mt < 4; ++mt) {
            const int m0 = mt * 16 + r;
#pragma unroll
            for (int j = 0; j < 2; ++j) {
                const int n = n0 + j * 8;
                atomicAdd(&out[(size_t)m0 * N + n],            Ms[mt][j][0]);
                atomicAdd(&out[(size_t)m0 * N + n + 1],        Ms[mt][j][1]);
                atomicAdd(&out[(size_t)(m0 + 8) * N + n],      Ms[mt][j][2]);
                atomicAdd(&out[(size_t)(m0 + 8) * N + n + 1],  Ms[mt][j][3]);
            }
        }
    }
}

// ---------------------------------------------------------------------------
// kernel_launch: inputs per metadata order: x, qweight, qzeros, scales, bias
// ---------------------------------------------------------------------------
extern "C" void kernel_launch(void* const* d_in, const int* in_sizes, int n_in,
                              void* d_out, int out_size) {
    (void)in_sizes; (void)n_in; (void)out_size;
    const float* x       = (const float*)d_in[0];
    const int*   qweight = (const int*)  d_in[1];
    const int*   qzeros  = (const int*)  d_in[2];
    const float* scales  = (const float*)d_in[3];
    const float* bias    = (const float*)d_in[4];
    float*       out     = (float*)d_out;

    // Idempotent, non-stream host call: safe under graph capture.
    cudaFuncSetAttribute(gptq_mma_kernel,
                         cudaFuncAttributeMaxDynamicSharedMemorySize, SMEM_BYTES);

    init_out_kernel<<<(M * N + 255) / 256, 256>>>(bias, out);
    prep_x_kernel<<<(M * (K / 8) + 255) / 256, 256>>>(x);

    dim3 grid(N / NTILE, KSPLIT);               // (172, 4)
    gptq_mma_kernel<<<grid, THREADS, SMEM_BYTES>>>(qweight, qzeros, scales, out);
}